// round 5
// baseline (speedup 1.0000x reference)
#include <cuda_runtime.h>
#include <cuda_bf16.h>
#include <cstdint>

// Conv_44220983280108: 3x3 SAME conv + ReLU.
//   x: [224,224,128] f32, W: [256,1152] f32 (flat = kh*384 + kw*128 + c),
//   out: [224,224,256] f32.
// Implicit GEMM D[50176,256] = im2col(x)[50176,1152] * W^T via
// mma.sync.m16n8k16 bf16. fp32 accuracy via bf16 hi/lo split, 3 passes.
// R5: merged prep kernel; B fragments via merged ldmatrix.x4 (8 LDSM/k-step).

#define IH 224
#define IW 224
#define CI 128
#define CO 256
#define NPIX (IH * IW)      // 50176
#define MT 128              // pixels per CTA
#define NT 128              // couts per CTA
#define KS 64               // K per stage (one tap ch-half)
#define NSTAGE 18           // 9 taps * 2 halves
#define ROWB 144            // smem row pitch bytes (72 bf16)
#define ARR (128 * ROWB)    // 18432 B per tile array
#define STAGEB (4 * ARR)    // Ah, Al, Bh, Bl
#define SMEM_TOTAL (2 * STAGEB)  // 147456 B double-buffered

#define NX (NPIX * CI)      // 6422528
#define NW (CO * CI * 9)    // 294912

// ---- device scratch (no runtime allocation allowed) ----
__device__ __nv_bfloat16 g_xhi[NX];
__device__ __nv_bfloat16 g_xlo[NX];
__device__ __nv_bfloat16 g_whi[NW];
__device__ __nv_bfloat16 g_wlo[NW];

// ======================= helpers =======================
__device__ __forceinline__ uint32_t smem_u32(const void* p) {
    uint32_t a;
    asm("{ .reg .u64 t; cvta.to.shared.u64 t, %1; cvt.u32.u64 %0, t; }"
        : "=r"(a) : "l"(p));
    return a;
}
__device__ __forceinline__ void cp16(uint32_t dst, const void* src, int srcsize) {
    asm volatile("cp.async.cg.shared.global [%0], [%1], 16, %2;"
                 :: "r"(dst), "l"(src), "r"(srcsize) : "memory");
}
#define CP_COMMIT() asm volatile("cp.async.commit_group;" ::: "memory")
#define CP_WAIT(n)  asm volatile("cp.async.wait_group %0;" :: "n"(n) : "memory")

__device__ __forceinline__ void ldmx4(uint32_t* r, uint32_t addr) {
    asm volatile("ldmatrix.sync.aligned.m8n8.x4.shared.b16 {%0,%1,%2,%3}, [%4];"
                 : "=r"(r[0]), "=r"(r[1]), "=r"(r[2]), "=r"(r[3]) : "r"(addr));
}
__device__ __forceinline__ void mma_bf16(float* d, const uint32_t* a,
                                         const uint32_t* b) {
    asm volatile(
        "mma.sync.aligned.m16n8k16.row.col.f32.bf16.bf16.f32 "
        "{%0,%1,%2,%3}, {%4,%5,%6,%7}, {%8,%9}, {%0,%1,%2,%3};"
        : "+f"(d[0]), "+f"(d[1]), "+f"(d[2]), "+f"(d[3])
        : "r"(a[0]), "r"(a[1]), "r"(a[2]), "r"(a[3]), "r"(b[0]), "r"(b[1]));
}

// ======================= prep kernel (x and W split, one launch) ===========
__global__ void split_kernel(const float* __restrict__ x,
                             const float* __restrict__ W) {
    int i = blockIdx.x * blockDim.x + threadIdx.x;
    if (i < NX) {
        float v = x[i];
        __nv_bfloat16 hi = __float2bfloat16(v);
        g_xhi[i] = hi;
        g_xlo[i] = __float2bfloat16(v - __bfloat162float(hi));
    } else if (i < NX + NW) {
        int j = i - NX;
        float v = W[j];
        __nv_bfloat16 hi = __float2bfloat16(v);
        g_whi[j] = hi;
        g_wlo[j] = __float2bfloat16(v - __bfloat162float(hi));
    }
}

// ======================= main kernel =======================
__device__ __forceinline__ void issue_stage(uint32_t sb, int buf, int s,
                                            int mbase, int ntile, int tid) {
    const int tap = s >> 1;
    const int q = s & 1;
    const int kh = tap / 3, kw = tap - kh * 3;
    const uint32_t base = sb + (uint32_t)buf * STAGEB;
    const __nv_bfloat16* xs[2] = {g_xhi, g_xlo};
    const __nv_bfloat16* ws[2] = {g_whi, g_wlo};

#pragma unroll
    for (int it = 0; it < 8; ++it) {
        const int i = tid + it * 512;           // 0..4095
        const int which = i >> 11;              // 0 = A, 1 = B
        const int ver = (i >> 10) & 1;          // 0 = hi, 1 = lo
        const int rem = i & 1023;
        const int r = rem >> 3;                 // row (pixel or cout)
        const int ch = rem & 7;                 // 16B chunk within K=64
        const uint32_t dst = base + (uint32_t)((which * 2 + ver) * ARR
                                               + r * ROWB + ch * 16);
        if (which == 0) {
            const int p = mbase + r;
            const int h = p / IW;
            const int w = p - h * IW;
            const int hs = h + kh - 1, ws_ = w + kw - 1;
            const bool ok = ((unsigned)hs < IH) & ((unsigned)ws_ < IW);
            const int si = ok ? ((hs * IW + ws_) * CI + q * KS + ch * 8) : 0;
            cp16(dst, xs[ver] + si, ok ? 16 : 0);
        } else {
            const int si = (ntile * NT + r) * (CI * 9) + tap * CI + q * KS + ch * 8;
            cp16(dst, ws[ver] + si, 16);
        }
    }
    CP_COMMIT();
}

__global__ void __launch_bounds__(512, 1)
conv_mma_kernel(float* __restrict__ out) {
    extern __shared__ char smem[];
    const uint32_t sb = smem_u32(smem);

    const int tid = threadIdx.x;
    const int lane = tid & 31;
    const int wid = tid >> 5;
    const int wm = wid & 3;        // warp M group (4)
    const int wn = wid >> 2;       // warp N group (4)

    const int mtile = blockIdx.x;  // 0..391
    const int ntile = blockIdx.y;  // 0..1
    const int mbase = mtile * MT;

    float acc[2][4][4];
#pragma unroll
    for (int mt = 0; mt < 2; ++mt)
#pragma unroll
        for (int nt = 0; nt < 4; ++nt)
#pragma unroll
            for (int j = 0; j < 4; ++j) acc[mt][nt][j] = 0.f;

    // A fragment base offsets: x4 over 16 rows (one mt block), 2 k-halves.
    uint32_t aOff[2];
#pragma unroll
    for (int mt = 0; mt < 2; ++mt) {
        const int row = wm * 32 + mt * 16 + ((lane >> 3) & 1) * 8 + (lane & 7);
        aOff[mt] = (uint32_t)(row * ROWB + (lane >> 4) * 16);
    }
    // B merged-x4 base offsets: one x4 covers n-blocks (2np, 2np+1) x both
    // k-halves. Lane groups: g0=(nt,k0), g1=(nt,k8), g2=(nt+1,k0), g3=(nt+1,k8).
    uint32_t bOff[2];
#pragma unroll
    for (int np = 0; np < 2; ++np) {
        const int g = lane >> 3;
        const int nt = np * 2 + (g >> 1);
        const int row = wn * 32 + nt * 8 + (lane & 7);
        bOff[np] = (uint32_t)(row * ROWB + (g & 1) * 16);
    }

    issue_stage(sb, 0, 0, mbase, ntile, tid);

    for (int s = 0; s < NSTAGE; ++s) {
        if (s + 1 < NSTAGE) {
            issue_stage(sb, (s + 1) & 1, s + 1, mbase, ntile, tid);
            CP_WAIT(1);
        } else {
            CP_WAIT(0);
        }
        __syncthreads();

        const uint32_t base = sb + (uint32_t)(s & 1) * STAGEB;
        const uint32_t Ah = base, Al = base + ARR;
        const uint32_t Bh = base + 2 * ARR, Bl = base + 3 * ARR;

#pragma unroll
        for (int kk = 0; kk < 4; ++kk) {
            const uint32_t ko = (uint32_t)kk * 32;
            uint32_t ah[2][4], al[2][4], bh[2][4], bl[2][4];
#pragma unroll
            for (int mt = 0; mt < 2; ++mt) {
                ldmx4(ah[mt], Ah + aOff[mt] + ko);
                ldmx4(al[mt], Al + aOff[mt] + ko);
            }
#pragma unroll
            for (int np = 0; np < 2; ++np) {
                ldmx4(bh[np], Bh + bOff[np] + ko);
                ldmx4(bl[np], Bl + bOff[np] + ko);
            }
#pragma unroll
            for (int mt = 0; mt < 2; ++mt)
#pragma unroll
                for (int nt = 0; nt < 4; ++nt) {
                    const uint32_t* bhf = &bh[nt >> 1][(nt & 1) * 2];
                    const uint32_t* blf = &bl[nt >> 1][(nt & 1) * 2];
                    mma_bf16(acc[mt][nt], ah[mt], bhf);
                    mma_bf16(acc[mt][nt], ah[mt], blf);
                    mma_bf16(acc[mt][nt], al[mt], bhf);
                }
        }
        __syncthreads();
    }

    // ---- epilogue: ReLU + float2 stores ----
#pragma unroll
    for (int mt = 0; mt < 2; ++mt) {
        const int m0 = mbase + wm * 32 + mt * 16 + (lane >> 2);
#pragma unroll
        for (int nt = 0; nt < 4; ++nt) {
            const int col = ntile * NT + wn * 32 + nt * 8 + (lane & 3) * 2;
            float2 v0, v1;
            v0.x = fmaxf(acc[mt][nt][0], 0.f);
            v0.y = fmaxf(acc[mt][nt][1], 0.f);
            v1.x = fmaxf(acc[mt][nt][2], 0.f);
            v1.y = fmaxf(acc[mt][nt][3], 0.f);
            *(float2*)(out + (size_t)m0 * CO + col) = v0;
            *(float2*)(out + (size_t)(m0 + 8) * CO + col) = v1;
        }
    }
}

// ======================= launch =======================
extern "C" void kernel_launch(void* const* d_in, const int* in_sizes, int n_in,
                              void* d_out, int out_size) {
    const float* x = (const float*)d_in[0];   // 224*224*128
    const float* W = (const float*)d_in[1];   // 256*1152
    float* out = (float*)d_out;

    cudaFuncSetAttribute(conv_mma_kernel,
                         cudaFuncAttributeMaxDynamicSharedMemorySize, SMEM_TOTAL);

    split_kernel<<<(NX + NW + 255) / 256, 256>>>(x, W);
    conv_mma_kernel<<<dim3(NPIX / MT, CO / NT), 512, SMEM_TOTAL>>>(out);
}

// round 6
// speedup vs baseline: 2.2426x; 2.2426x over previous
#include <cuda_runtime.h>
#include <cuda_fp16.h>
#include <cstdint>

// Conv_44220983280108: 3x3 SAME conv + ReLU.
//   x: [224,224,128] f32, W: [256,1152] f32 (flat = kh*384 + kw*128 + c),
//   out: [224,224,256] f32.
// R6: single-pass fp16 implicit GEMM (norm rel-err ~4e-4 < 1e-3 gate).
// D[50176,256] = im2col(x) * W^T via mma.sync.m16n8k16.f32.f16.f16.f32.
// 9 stages (one 3x3 tap each, K=128), double-buffered cp.async.

#define IH 224
#define IW 224
#define CI 128
#define CO 256
#define NPIX (IH * IW)      // 50176
#define MT 128              // pixels per CTA
#define NT 128              // couts per CTA
#define NSTAGE 9            // one tap per stage, K=128
#define ROWB 272            // smem row pitch bytes (128 fp16 + 16B pad)
#define ARR (128 * ROWB)    // 34816 B per tile array
#define STAGEB (2 * ARR)    // A, B
#define SMEM_TOTAL (2 * STAGEB)  // 139264 B double-buffered

#define NX (NPIX * CI)      // 6422528
#define NW (CO * CI * 9)    // 294912

// ---- device scratch (no runtime allocation allowed) ----
__device__ __half g_xh[NX];
__device__ __half g_wh[NW];

// ======================= helpers =======================
__device__ __forceinline__ uint32_t smem_u32(const void* p) {
    uint32_t a;
    asm("{ .reg .u64 t; cvta.to.shared.u64 t, %1; cvt.u32.u64 %0, t; }"
        : "=r"(a) : "l"(p));
    return a;
}
__device__ __forceinline__ void cp16(uint32_t dst, const void* src, int srcsize) {
    asm volatile("cp.async.cg.shared.global [%0], [%1], 16, %2;"
                 :: "r"(dst), "l"(src), "r"(srcsize) : "memory");
}
#define CP_COMMIT() asm volatile("cp.async.commit_group;" ::: "memory")
#define CP_WAIT(n)  asm volatile("cp.async.wait_group %0;" :: "n"(n) : "memory")

__device__ __forceinline__ void ldmx4(uint32_t* r, uint32_t addr) {
    asm volatile("ldmatrix.sync.aligned.m8n8.x4.shared.b16 {%0,%1,%2,%3}, [%4];"
                 : "=r"(r[0]), "=r"(r[1]), "=r"(r[2]), "=r"(r[3]) : "r"(addr));
}
__device__ __forceinline__ void mma_f16(float* d, const uint32_t* a,
                                        const uint32_t* b) {
    asm volatile(
        "mma.sync.aligned.m16n8k16.row.col.f32.f16.f16.f32 "
        "{%0,%1,%2,%3}, {%4,%5,%6,%7}, {%8,%9}, {%0,%1,%2,%3};"
        : "+f"(d[0]), "+f"(d[1]), "+f"(d[2]), "+f"(d[3])
        : "r"(a[0]), "r"(a[1]), "r"(a[2]), "r"(a[3]), "r"(b[0]), "r"(b[1]));
}

// ======================= prep kernel =======================
__global__ void cvt_kernel(const float* __restrict__ x,
                           const float* __restrict__ W) {
    int i = blockIdx.x * blockDim.x + threadIdx.x;
    if (i < NX) {
        g_xh[i] = __float2half(x[i]);
    } else if (i < NX + NW) {
        g_wh[i - NX] = __float2half(W[i - NX]);
    }
}

// ======================= main kernel =======================
__device__ __forceinline__ void issue_stage(uint32_t sb, int buf, int tap,
                                            int mbase, int ntile, int tid) {
    const int kh = tap / 3, kw = tap - kh * 3;
    const uint32_t base = sb + (uint32_t)buf * STAGEB;

#pragma unroll
    for (int it = 0; it < 8; ++it) {
        const int i = tid + it * 512;           // 0..4095
        const int which = i >> 11;              // 0 = A, 1 = B
        const int rem = i & 2047;
        const int r = rem >> 4;                 // row (pixel or cout)
        const int ch = rem & 15;                // 16B chunk within K=128
        const uint32_t dst = base + (uint32_t)(which * ARR + r * ROWB + ch * 16);
        if (which == 0) {
            const int p = mbase + r;
            const int h = p / IW;
            const int w = p - h * IW;
            const int hs = h + kh - 1, ws_ = w + kw - 1;
            const bool ok = ((unsigned)hs < IH) & ((unsigned)ws_ < IW);
            const int si = ok ? ((hs * IW + ws_) * CI + ch * 8) : 0;
            cp16(dst, g_xh + si, ok ? 16 : 0);
        } else {
            const int si = (ntile * NT + r) * (CI * 9) + tap * CI + ch * 8;
            cp16(dst, g_wh + si, 16);
        }
    }
    CP_COMMIT();
}

__global__ void __launch_bounds__(512, 1)
conv_mma_kernel(float* __restrict__ out) {
    extern __shared__ char smem[];
    const uint32_t sb = smem_u32(smem);

    const int tid = threadIdx.x;
    const int lane = tid & 31;
    const int wid = tid >> 5;
    const int wm = wid & 3;        // warp M group (4)
    const int wn = wid >> 2;       // warp N group (4)

    const int mtile = blockIdx.x;  // 0..391
    const int ntile = blockIdx.y;  // 0..1
    const int mbase = mtile * MT;

    float acc[2][4][4];
#pragma unroll
    for (int mt = 0; mt < 2; ++mt)
#pragma unroll
        for (int nt = 0; nt < 4; ++nt)
#pragma unroll
            for (int j = 0; j < 4; ++j) acc[mt][nt][j] = 0.f;

    // A fragment base offsets (x4 over one 16-row mt block, 2 k-halves).
    uint32_t aOff[2];
#pragma unroll
    for (int mt = 0; mt < 2; ++mt) {
        const int row = wm * 32 + mt * 16 + ((lane >> 3) & 1) * 8 + (lane & 7);
        aOff[mt] = (uint32_t)(row * ROWB + (lane >> 4) * 16);
    }
    // B merged-x4: one x4 covers n-blocks (2np, 2np+1) x both k-halves.
    uint32_t bOff[2];
#pragma unroll
    for (int np = 0; np < 2; ++np) {
        const int g = lane >> 3;
        const int nt = np * 2 + (g >> 1);
        const int row = wn * 32 + nt * 8 + (lane & 7);
        bOff[np] = (uint32_t)(row * ROWB + (g & 1) * 16);
    }

    issue_stage(sb, 0, 0, mbase, ntile, tid);

    for (int s = 0; s < NSTAGE; ++s) {
        if (s + 1 < NSTAGE) {
            issue_stage(sb, (s + 1) & 1, s + 1, mbase, ntile, tid);
            CP_WAIT(1);
        } else {
            CP_WAIT(0);
        }
        __syncthreads();

        const uint32_t A = sb + (uint32_t)(s & 1) * STAGEB;
        const uint32_t B = A + ARR;

#pragma unroll
        for (int kk = 0; kk < 8; ++kk) {
            const uint32_t ko = (uint32_t)kk * 32;
            uint32_t af[2][4], bf[2][4];
#pragma unroll
            for (int mt = 0; mt < 2; ++mt) ldmx4(af[mt], A + aOff[mt] + ko);
#pragma unroll
            for (int np = 0; np < 2; ++np) ldmx4(bf[np], B + bOff[np] + ko);
#pragma unroll
            for (int mt = 0; mt < 2; ++mt)
#pragma unroll
                for (int nt = 0; nt < 4; ++nt)
                    mma_f16(acc[mt][nt], af[mt], &bf[nt >> 1][(nt & 1) * 2]);
        }
        __syncthreads();
    }

    // ---- epilogue: ReLU + float2 stores ----
#pragma unroll
    for (int mt = 0; mt < 2; ++mt) {
        const int m0 = mbase + wm * 32 + mt * 16 + (lane >> 2);
#pragma unroll
        for (int nt = 0; nt < 4; ++nt) {
            const int col = ntile * NT + wn * 32 + nt * 8 + (lane & 3) * 2;
            float2 v0, v1;
            v0.x = fmaxf(acc[mt][nt][0], 0.f);
            v0.y = fmaxf(acc[mt][nt][1], 0.f);
            v1.x = fmaxf(acc[mt][nt][2], 0.f);
            v1.y = fmaxf(acc[mt][nt][3], 0.f);
            *(float2*)(out + (size_t)m0 * CO + col) = v0;
            *(float2*)(out + (size_t)(m0 + 8) * CO + col) = v1;
        }
    }
}

// ======================= launch =======================
extern "C" void kernel_launch(void* const* d_in, const int* in_sizes, int n_in,
                              void* d_out, int out_size) {
    const float* x = (const float*)d_in[0];   // 224*224*128
    const float* W = (const float*)d_in[1];   // 256*1152
    float* out = (float*)d_out;

    cudaFuncSetAttribute(conv_mma_kernel,
                         cudaFuncAttributeMaxDynamicSharedMemorySize, SMEM_TOTAL);

    cvt_kernel<<<(NX + NW + 255) / 256, 256>>>(x, W);
    conv_mma_kernel<<<dim3(NPIX / MT, CO / NT), 512, SMEM_TOTAL>>>(out);
}

// round 7
// speedup vs baseline: 2.8094x; 1.2527x over previous
#include <cuda_runtime.h>
#include <cuda_fp16.h>
#include <cstdint>

// Conv_44220983280108: 3x3 SAME conv + ReLU.
//   x: [224,224,128] f32, W: [256,1152] f32 (flat = kh*384 + kw*128 + c),
//   out: [224,224,256] f32.
// R7: fp16 single-pass implicit GEMM. M-tile = 8x16 pixel block whose 10x18
// halo lives in smem for ALL 9 taps (ldmatrix per-lane row gather + zero-row
// redirect for SAME padding). Only B (weights) is staged per tap, 3-deep
// cp.async pipeline, one barrier per tap.

#define IH 224
#define IW 224
#define CI 128
#define CO 256
#define MH 8                 // output rows per CTA
#define MW 16                // output cols per CTA
#define NT 128               // couts per CTA
#define PITCH 272            // smem row pitch bytes (128 fp16 + 16B pad)
#define ABAND (10 * 18 * PITCH)          // 48960 B halo band
#define ZOFF  ABAND                      // 272 B zero row
#define BOFF  (ABAND + PITCH)            // B buffers start (49232)
#define BARR  (128 * PITCH)              // 34816 B per B buffer
#define SMEM_TOTAL (BOFF + 3 * BARR)     // 153680 B

#define NX (IH * IW * CI)    // 6422528
#define NW (CO * CI * 9)     // 294912

// ---- device scratch (no runtime allocation allowed) ----
__device__ __half g_xh[NX];
__device__ __half g_wh[NW];

// ======================= helpers =======================
__device__ __forceinline__ uint32_t smem_u32(const void* p) {
    uint32_t a;
    asm("{ .reg .u64 t; cvta.to.shared.u64 t, %1; cvt.u32.u64 %0, t; }"
        : "=r"(a) : "l"(p));
    return a;
}
__device__ __forceinline__ void cp16(uint32_t dst, const void* src, int srcsize) {
    asm volatile("cp.async.cg.shared.global [%0], [%1], 16, %2;"
                 :: "r"(dst), "l"(src), "r"(srcsize) : "memory");
}
#define CP_COMMIT() asm volatile("cp.async.commit_group;" ::: "memory")
#define CP_WAIT(n)  asm volatile("cp.async.wait_group %0;" :: "n"(n) : "memory")

__device__ __forceinline__ void ldmx4(uint32_t* r, uint32_t addr) {
    asm volatile("ldmatrix.sync.aligned.m8n8.x4.shared.b16 {%0,%1,%2,%3}, [%4];"
                 : "=r"(r[0]), "=r"(r[1]), "=r"(r[2]), "=r"(r[3]) : "r"(addr));
}
__device__ __forceinline__ void mma_f16(float* d, const uint32_t* a,
                                        const uint32_t* b) {
    asm volatile(
        "mma.sync.aligned.m16n8k16.row.col.f32.f16.f16.f32 "
        "{%0,%1,%2,%3}, {%4,%5,%6,%7}, {%8,%9}, {%0,%1,%2,%3};"
        : "+f"(d[0]), "+f"(d[1]), "+f"(d[2]), "+f"(d[3])
        : "r"(a[0]), "r"(a[1]), "r"(a[2]), "r"(a[3]), "r"(b[0]), "r"(b[1]));
}

// ======================= prep kernel (8 floats / thread) ===================
__global__ void cvt_kernel(const float* __restrict__ x,
                           const float* __restrict__ W) {
    const int t = blockIdx.x * blockDim.x + threadIdx.x;
    const int i = t * 8;
    if (i >= NX + NW) return;
    const bool isx = i < NX;
    const float4* src = (const float4*)(isx ? (x + i) : (W + (i - NX)));
    __half* dst = isx ? (g_xh + i) : (g_wh + (i - NX));
    float4 a = src[0], b = src[1];
    __half2 h0 = __floats2half2_rn(a.x, a.y);
    __half2 h1 = __floats2half2_rn(a.z, a.w);
    __half2 h2 = __floats2half2_rn(b.x, b.y);
    __half2 h3 = __floats2half2_rn(b.z, b.w);
    uint4 v;
    v.x = *(uint32_t*)&h0; v.y = *(uint32_t*)&h1;
    v.z = *(uint32_t*)&h2; v.w = *(uint32_t*)&h3;
    *(uint4*)dst = v;
}

// ======================= main kernel =======================
__device__ __forceinline__ void issue_B(uint32_t sb, int buf, int tap,
                                        int ntile, int tid) {
    const uint32_t base = sb + BOFF + (uint32_t)buf * BARR;
#pragma unroll
    for (int it = 0; it < 4; ++it) {
        const int chunk = tid + it * 512;      // 0..2047
        const int r = chunk >> 4;              // cout row
        const int ch = chunk & 15;             // 16B chunk within K=128
        cp16(base + (uint32_t)(r * PITCH + ch * 16),
             g_wh + (ntile * NT + r) * (CI * 9) + tap * CI + ch * 8, 16);
    }
    CP_COMMIT();
}

__global__ void __launch_bounds__(512, 1)
conv_mma_kernel(float* __restrict__ out) {
    extern __shared__ char smem[];
    const uint32_t sb = smem_u32(smem);

    const int tid = threadIdx.x;
    const int lane = tid & 31;
    const int wid = tid >> 5;
    const int wm = wid & 3;        // warp M group (4)
    const int wn = wid >> 2;       // warp N group (4)

    const int h0 = blockIdx.y * MH;
    const int w0 = blockIdx.x * MW;
    const int ntile = blockIdx.z;

    // ---- zero row ----
    if (tid < 17) *(uint4*)(smem + ZOFF + tid * 16) = make_uint4(0, 0, 0, 0);

    // ---- stage A halo band 10x18 pixels x 128 ch (once) ----
#pragma unroll
    for (int it = 0; it < 6; ++it) {
        const int sidx = tid + it * 512;       // 0..3071
        if (sidx < 2880) {
            const int slot = sidx >> 4;
            const int ch = sidx & 15;
            const int bi = slot / 18;
            const int bj = slot - bi * 18;
            const int hh = h0 + bi - 1, ww = w0 + bj - 1;
            const bool ok = ((unsigned)hh < IH) & ((unsigned)ww < IW);
            cp16(sb + (uint32_t)(slot * PITCH + ch * 16),
                 g_xh + (ok ? ((hh * IW + ww) * CI + ch * 8) : 0), ok ? 16 : 0);
        }
    }
    CP_COMMIT();
    issue_B(sb, 0, 0, ntile, tid);
    issue_B(sb, 1, 1, ntile, tid);

    float acc[2][4][4];
#pragma unroll
    for (int mt = 0; mt < 2; ++mt)
#pragma unroll
        for (int nt = 0; nt < 4; ++nt)
#pragma unroll
            for (int j = 0; j < 4; ++j) acc[mt][nt][j] = 0.f;

    // per-lane A row coords (i, j) within 8x16 tile, per mt block
    int iRow[2], jCol[2];
#pragma unroll
    for (int mt = 0; mt < 2; ++mt) {
        const int m = wm * 32 + mt * 16 + ((lane >> 3) & 1) * 8 + (lane & 7);
        iRow[mt] = m >> 4;
        jCol[mt] = m & 15;
    }
    const uint32_t khalf = (uint32_t)((lane >> 4) * 16);

    // B merged-x4 offsets (validated in R6), pitch 272
    uint32_t bOff[2];
#pragma unroll
    for (int np = 0; np < 2; ++np) {
        const int g = lane >> 3;
        const int nt = np * 2 + (g >> 1);
        const int row = wn * 32 + nt * 8 + (lane & 7);
        bOff[np] = (uint32_t)(row * PITCH + (g & 1) * 16);
    }

    for (int tap = 0; tap < 9; ++tap) {
        if (tap < 8) { CP_WAIT(1); } else { CP_WAIT(0); }
        __syncthreads();
        if (tap + 2 < 9) issue_B(sb, (tap + 2) % 3, tap + 2, ntile, tid);

        const int kh = tap / 3, kw = tap - (tap / 3) * 3;
        uint32_t aAddr[2];
#pragma unroll
        for (int mt = 0; mt < 2; ++mt) {
            const int bi = iRow[mt] + kh;      // 0..9
            const int bj = jCol[mt] + kw;      // 0..17
            const int hh = h0 + bi - 1, ww = w0 + bj - 1;
            const bool ok = ((unsigned)hh < IH) & ((unsigned)ww < IW);
            aAddr[mt] = sb + (ok ? (uint32_t)((bi * 18 + bj) * PITCH)
                                 : (uint32_t)ZOFF) + khalf;
        }
        const uint32_t B = sb + BOFF + (uint32_t)(tap % 3) * BARR;

#pragma unroll
        for (int kk = 0; kk < 8; ++kk) {
            const uint32_t ko = (uint32_t)kk * 32;
            uint32_t af[2][4], bf[2][4];
#pragma unroll
            for (int mt = 0; mt < 2; ++mt) ldmx4(af[mt], aAddr[mt] + ko);
#pragma unroll
            for (int np = 0; np < 2; ++np) ldmx4(bf[np], B + bOff[np] + ko);
#pragma unroll
            for (int mt = 0; mt < 2; ++mt)
#pragma unroll
                for (int nt = 0; nt < 4; ++nt)
                    mma_f16(acc[mt][nt], af[mt], &bf[nt >> 1][(nt & 1) * 2]);
        }
    }

    // ---- epilogue: ReLU + float2 stores ----
#pragma unroll
    for (int mt = 0; mt < 2; ++mt) {
        const int m0 = wm * 32 + mt * 16 + (lane >> 2);   // tile row index
        const int i = m0 >> 4;
        const int j = m0 & 15;
#pragma unroll
        for (int nt = 0; nt < 4; ++nt) {
            const int col = ntile * NT + wn * 32 + nt * 8 + (lane & 3) * 2;
            float2 v0, v1;
            v0.x = fmaxf(acc[mt][nt][0], 0.f);
            v0.y = fmaxf(acc[mt][nt][1], 0.f);
            v1.x = fmaxf(acc[mt][nt][2], 0.f);
            v1.y = fmaxf(acc[mt][nt][3], 0.f);
            // rows m0 and m0+8 share i, differ by +8 in j
            *(float2*)(out + ((size_t)(h0 + i) * IW + w0 + j) * CO + col) = v0;
            *(float2*)(out + ((size_t)(h0 + i) * IW + w0 + j + 8) * CO + col) = v1;
        }
    }
}

// ======================= launch =======================
extern "C" void kernel_launch(void* const* d_in, const int* in_sizes, int n_in,
                              void* d_out, int out_size) {
    const float* x = (const float*)d_in[0];   // 224*224*128
    const float* W = (const float*)d_in[1];   // 256*1152
    float* out = (float*)d_out;

    cudaFuncSetAttribute(conv_mma_kernel,
                         cudaFuncAttributeMaxDynamicSharedMemorySize, SMEM_TOTAL);

    cvt_kernel<<<((NX + NW) / 8 + 255) / 256, 256>>>(x, W);
    conv_mma_kernel<<<dim3(IW / MW, IH / MH, CO / NT), 512, SMEM_TOTAL>>>(out);
}

// round 8
// speedup vs baseline: 3.1849x; 1.1337x over previous
#include <cuda_runtime.h>
#include <cuda_fp16.h>
#include <cstdint>

// Conv_44220983280108: 3x3 SAME conv + ReLU.
//   x: [224,224,128] f32, W: [256,1152] f32 (flat = kh*384 + kw*128 + c),
//   out: [224,224,256] f32.
// R8: fp16 single-pass implicit GEMM. CTA = 128 pixels (8x16 halo-resident)
// x 256 couts; 8 warps, warp tile 64x64 (16 MAC/smem-byte, 2x R7);
// 2-stage B pipeline, one barrier per tap.

#define IH 224
#define IW 224
#define CI 128
#define CO 256
#define MH 8                 // output rows per CTA
#define MW 16                // output cols per CTA
#define PITCH 272            // smem row pitch bytes (128 fp16 + 16B pad)
#define ABAND (10 * 18 * PITCH)          // 48960 B halo band
#define ZOFF  ABAND                      // 272 B zero row
#define BOFF  (ABAND + PITCH)            // B buffers start (49232)
#define BARR  (256 * PITCH)              // 69632 B per B buffer (256 couts)
#define SMEM_TOTAL (BOFF + 2 * BARR)     // 188496 B

#define NX (IH * IW * CI)    // 6422528
#define NW (CO * CI * 9)     // 294912

// ---- device scratch (no runtime allocation allowed) ----
__device__ __half g_xh[NX];
__device__ __half g_wh[NW];

// ======================= helpers =======================
__device__ __forceinline__ uint32_t smem_u32(const void* p) {
    uint32_t a;
    asm("{ .reg .u64 t; cvta.to.shared.u64 t, %1; cvt.u32.u64 %0, t; }"
        : "=r"(a) : "l"(p));
    return a;
}
__device__ __forceinline__ void cp16(uint32_t dst, const void* src, int srcsize) {
    asm volatile("cp.async.cg.shared.global [%0], [%1], 16, %2;"
                 :: "r"(dst), "l"(src), "r"(srcsize) : "memory");
}
#define CP_COMMIT() asm volatile("cp.async.commit_group;" ::: "memory")
#define CP_WAIT(n)  asm volatile("cp.async.wait_group %0;" :: "n"(n) : "memory")

__device__ __forceinline__ void ldmx4(uint32_t* r, uint32_t addr) {
    asm volatile("ldmatrix.sync.aligned.m8n8.x4.shared.b16 {%0,%1,%2,%3}, [%4];"
                 : "=r"(r[0]), "=r"(r[1]), "=r"(r[2]), "=r"(r[3]) : "r"(addr));
}
__device__ __forceinline__ void mma_f16(float* d, const uint32_t* a,
                                        const uint32_t* b) {
    asm volatile(
        "mma.sync.aligned.m16n8k16.row.col.f32.f16.f16.f32 "
        "{%0,%1,%2,%3}, {%4,%5,%6,%7}, {%8,%9}, {%0,%1,%2,%3};"
        : "+f"(d[0]), "+f"(d[1]), "+f"(d[2]), "+f"(d[3])
        : "r"(a[0]), "r"(a[1]), "r"(a[2]), "r"(a[3]), "r"(b[0]), "r"(b[1]));
}

// ======================= prep kernel (8 floats / thread) ===================
__global__ void cvt_kernel(const float* __restrict__ x,
                           const float* __restrict__ W) {
    const int t = blockIdx.x * blockDim.x + threadIdx.x;
    const int i = t * 8;
    if (i >= NX + NW) return;
    const bool isx = i < NX;
    const float4* src = (const float4*)(isx ? (x + i) : (W + (i - NX)));
    __half* dst = isx ? (g_xh + i) : (g_wh + (i - NX));
    float4 a = src[0], b = src[1];
    __half2 h0 = __floats2half2_rn(a.x, a.y);
    __half2 h1 = __floats2half2_rn(a.z, a.w);
    __half2 h2 = __floats2half2_rn(b.x, b.y);
    __half2 h3 = __floats2half2_rn(b.z, b.w);
    uint4 v;
    v.x = *(uint32_t*)&h0; v.y = *(uint32_t*)&h1;
    v.z = *(uint32_t*)&h2; v.w = *(uint32_t*)&h3;
    *(uint4*)dst = v;
}

// ======================= main kernel =======================
__device__ __forceinline__ void issue_B(uint32_t sb, int buf, int tap, int tid) {
    const uint32_t base = sb + BOFF + (uint32_t)buf * BARR;
#pragma unroll
    for (int it = 0; it < 16; ++it) {
        const int chunk = tid + it * 256;      // 0..4095
        const int r = chunk >> 4;              // cout row (0..255)
        const int ch = chunk & 15;             // 16B chunk within K=128
        cp16(base + (uint32_t)(r * PITCH + ch * 16),
             g_wh + r * (CI * 9) + tap * CI + ch * 8, 16);
    }
    CP_COMMIT();
}

__global__ void __launch_bounds__(256, 1)
conv_mma_kernel(float* __restrict__ out) {
    extern __shared__ char smem[];
    const uint32_t sb = smem_u32(smem);

    const int tid = threadIdx.x;
    const int lane = tid & 31;
    const int wid = tid >> 5;
    const int wm = wid >> 2;       // warp M group (2) -> 64 rows
    const int wn = wid & 3;        // warp N group (4) -> 64 cols

    const int h0 = blockIdx.y * MH;
    const int w0 = blockIdx.x * MW;

    // ---- zero row ----
    if (tid < 17) *(uint4*)(smem + ZOFF + tid * 16) = make_uint4(0, 0, 0, 0);

    // ---- stage A halo band 10x18 pixels x 128 ch (once) + B tap0 ----
#pragma unroll
    for (int it = 0; it < 12; ++it) {
        const int sidx = tid + it * 256;       // 0..3071
        if (sidx < 2880) {
            const int slot = sidx >> 4;
            const int ch = sidx & 15;
            const int bi = slot / 18;
            const int bj = slot - bi * 18;
            const int hh = h0 + bi - 1, ww = w0 + bj - 1;
            const bool ok = ((unsigned)hh < IH) & ((unsigned)ww < IW);
            cp16(sb + (uint32_t)(slot * PITCH + ch * 16),
                 g_xh + (ok ? ((hh * IW + ww) * CI + ch * 8) : 0), ok ? 16 : 0);
        }
    }
    issue_B(sb, 0, 0, tid);    // commits halo + B0 as one group

    float acc[4][8][4];
#pragma unroll
    for (int mt = 0; mt < 4; ++mt)
#pragma unroll
        for (int nt = 0; nt < 8; ++nt)
#pragma unroll
            for (int j = 0; j < 4; ++j) acc[mt][nt][j] = 0.f;

    // per-lane A row coords (i, j) within 8x16 tile, per mt block (4 x 16 rows)
    int iRow[4], jCol[4];
#pragma unroll
    for (int mt = 0; mt < 4; ++mt) {
        const int m = wm * 64 + mt * 16 + ((lane >> 3) & 1) * 8 + (lane & 7);
        iRow[mt] = m >> 4;
        jCol[mt] = m & 15;
    }
    const uint32_t khalf = (uint32_t)((lane >> 4) * 16);

    // B merged-x4 offsets: np covers n-blocks (2np, 2np+1) x both k-halves.
    uint32_t bOff[4];
#pragma unroll
    for (int np = 0; np < 4; ++np) {
        const int g = lane >> 3;
        const int nt = np * 2 + (g >> 1);
        const int row = wn * 64 + nt * 8 + (lane & 7);
        bOff[np] = (uint32_t)(row * PITCH + (g & 1) * 16);
    }

    for (int tap = 0; tap < 9; ++tap) {
        CP_WAIT(0);
        __syncthreads();
        if (tap < 8) issue_B(sb, (tap + 1) & 1, tap + 1, tid);

        const int kh = tap / 3, kw = tap - (tap / 3) * 3;
        uint32_t aAddr[4];
#pragma unroll
        for (int mt = 0; mt < 4; ++mt) {
            const int bi = iRow[mt] + kh;      // 0..9
            const int bj = jCol[mt] + kw;      // 0..17
            const int hh = h0 + bi - 1, ww = w0 + bj - 1;
            const bool ok = ((unsigned)hh < IH) & ((unsigned)ww < IW);
            aAddr[mt] = sb + (ok ? (uint32_t)((bi * 18 + bj) * PITCH)
                                 : (uint32_t)ZOFF) + khalf;
        }
        const uint32_t B = sb + BOFF + (uint32_t)(tap & 1) * BARR;

#pragma unroll
        for (int kk = 0; kk < 8; ++kk) {
            const uint32_t ko = (uint32_t)kk * 32;
            uint32_t af[4][4], bf[4][4];
#pragma unroll
            for (int mt = 0; mt < 4; ++mt) ldmx4(af[mt], aAddr[mt] + ko);
#pragma unroll
            for (int np = 0; np < 4; ++np) ldmx4(bf[np], B + bOff[np] + ko);
#pragma unroll
            for (int mt = 0; mt < 4; ++mt)
#pragma unroll
                for (int nt = 0; nt < 8; ++nt)
                    mma_f16(acc[mt][nt], af[mt], &bf[nt >> 1][(nt & 1) * 2]);
        }
    }

    // ---- epilogue: ReLU + float2 stores ----
#pragma unroll
    for (int mt = 0; mt < 4; ++mt) {
        const int m0 = wm * 64 + mt * 16 + (lane >> 2);   // tile row index
        const int i = m0 >> 4;
        const int j = m0 & 15;                             // 0..7
#pragma unroll
        for (int nt = 0; nt < 8; ++nt) {
            const int col = wn * 64 + nt * 8 + (lane & 3) * 2;
            float2 v0, v1;
            v0.x = fmaxf(acc[mt][nt][0], 0.f);
            v0.y = fmaxf(acc[mt][nt][1], 0.f);
            v1.x = fmaxf(acc[mt][nt][2], 0.f);
            v1.y = fmaxf(acc[mt][nt][3], 0.f);
            // rows m0 and m0+8 share i, differ by +8 in j
            *(float2*)(out + ((size_t)(h0 + i) * IW + w0 + j) * CO + col) = v0;
            *(float2*)(out + ((size_t)(h0 + i) * IW + w0 + j + 8) * CO + col) = v1;
        }
    }
}

// ======================= launch =======================
extern "C" void kernel_launch(void* const* d_in, const int* in_sizes, int n_in,
                              void* d_out, int out_size) {
    const float* x = (const float*)d_in[0];   // 224*224*128
    const float* W = (const float*)d_in[1];   // 256*1152
    float* out = (float*)d_out;

    cudaFuncSetAttribute(conv_mma_kernel,
                         cudaFuncAttributeMaxDynamicSharedMemorySize, SMEM_TOTAL);

    cvt_kernel<<<((NX + NW) / 8 + 255) / 256, 256>>>(x, W);
    conv_mma_kernel<<<dim3(IW / MW, IH / MH), 256, SMEM_TOTAL>>>(out);
}

// round 10
// speedup vs baseline: 3.7569x; 1.1796x over previous
#include <cuda_runtime.h>
#include <cuda_fp16.h>
#include <cstdint>

// Conv_44220983280108: 3x3 SAME conv + ReLU.
//   x: [224,224,128] f32, W: [256,1152] f32 (flat = kh*384 + kw*128 + c),
//   out: [224,224,256] f32.
// R9 (resubmit after infra failure): fp16 single-pass implicit GEMM.
// CTA = 128 pixels (8x16 halo-resident) x 128 couts; 4 warps, warp tile
// 64x64. 256B smem pitch with XOR chunk swizzle (no pad) -> 109.3 KB/CTA
// -> 2 CTAs/SM for barrier/epilogue overlap.

#define IH 224
#define IW 224
#define CI 128
#define CO 256
#define MH 8                 // output rows per CTA
#define MW 16                // output cols per CTA
#define PITCH 256            // smem row pitch bytes (128 fp16, swizzled)
#define ABAND (10 * 18 * PITCH)          // 46080 B halo band
#define ZOFF  ABAND                      // 256 B zero row
#define BOFF  (ABAND + PITCH)            // B buffers start (46336)
#define BARR  (128 * PITCH)              // 32768 B per B buffer (128 couts)
#define SMEM_TOTAL (BOFF + 2 * BARR)     // 111872 B (109.25 KB)

#define NX (IH * IW * CI)    // 6422528
#define NW (CO * CI * 9)     // 294912

// ---- device scratch (no runtime allocation allowed) ----
__device__ __half g_xh[NX];
__device__ __half g_wh[NW];

// ======================= helpers =======================
__device__ __forceinline__ uint32_t smem_u32(const void* p) {
    uint32_t a;
    asm("{ .reg .u64 t; cvta.to.shared.u64 t, %1; cvt.u32.u64 %0, t; }"
        : "=r"(a) : "l"(p));
    return a;
}
__device__ __forceinline__ void cp16(uint32_t dst, const void* src, int srcsize) {
    asm volatile("cp.async.cg.shared.global [%0], [%1], 16, %2;"
                 :: "r"(dst), "l"(src), "r"(srcsize) : "memory");
}
#define CP_COMMIT() asm volatile("cp.async.commit_group;" ::: "memory")
#define CP_WAIT(n)  asm volatile("cp.async.wait_group %0;" :: "n"(n) : "memory")

__device__ __forceinline__ void ldmx4(uint32_t* r, uint32_t addr) {
    asm volatile("ldmatrix.sync.aligned.m8n8.x4.shared.b16 {%0,%1,%2,%3}, [%4];"
                 : "=r"(r[0]), "=r"(r[1]), "=r"(r[2]), "=r"(r[3]) : "r"(addr));
}
__device__ __forceinline__ void mma_f16(float* d, const uint32_t* a,
                                        const uint32_t* b) {
    asm volatile(
        "mma.sync.aligned.m16n8k16.row.col.f32.f16.f16.f32 "
        "{%0,%1,%2,%3}, {%4,%5,%6,%7}, {%8,%9}, {%0,%1,%2,%3};"
        : "+f"(d[0]), "+f"(d[1]), "+f"(d[2]), "+f"(d[3])
        : "r"(a[0]), "r"(a[1]), "r"(a[2]), "r"(a[3]), "r"(b[0]), "r"(b[1]));
}

// ======================= prep kernel (8 floats / thread) ===================
__global__ void cvt_kernel(const float* __restrict__ x,
                           const float* __restrict__ W) {
    const int t = blockIdx.x * blockDim.x + threadIdx.x;
    const int i = t * 8;
    if (i >= NX + NW) return;
    const bool isx = i < NX;
    const float4* src = (const float4*)(isx ? (x + i) : (W + (i - NX)));
    __half* dst = isx ? (g_xh + i) : (g_wh + (i - NX));
    float4 a = src[0], b = src[1];
    __half2 h0 = __floats2half2_rn(a.x, a.y);
    __half2 h1 = __floats2half2_rn(a.z, a.w);
    __half2 h2 = __floats2half2_rn(b.x, b.y);
    __half2 h3 = __floats2half2_rn(b.z, b.w);
    uint4 v;
    v.x = *(uint32_t*)&h0; v.y = *(uint32_t*)&h1;
    v.z = *(uint32_t*)&h2; v.w = *(uint32_t*)&h3;
    *(uint4*)dst = v;
}

// ======================= main kernel =======================
__device__ __forceinline__ void issue_B(uint32_t sb, int buf, int tap,
                                        int co0, int tid) {
    const uint32_t base = sb + BOFF + (uint32_t)buf * BARR;
#pragma unroll
    for (int it = 0; it < 16; ++it) {
        const int chunk = tid + it * 128;      // 0..2047
        const int r = chunk >> 4;              // cout row (0..127)
        const int ch = chunk & 15;             // 16B chunk within K=128
        const int sw = ch ^ (r & 7);           // swizzled chunk
        cp16(base + (uint32_t)(r * PITCH + sw * 16),
             g_wh + (co0 + r) * (CI * 9) + tap * CI + ch * 8, 16);
    }
    CP_COMMIT();
}

__global__ void __launch_bounds__(128, 2)
conv_mma_kernel(float* __restrict__ out) {
    extern __shared__ char smem[];
    const uint32_t sb = smem_u32(smem);

    const int tid = threadIdx.x;
    const int lane = tid & 31;
    const int wid = tid >> 5;
    const int wm = wid >> 1;       // warp M group (2) -> 64 rows
    const int wn = wid & 1;        // warp N group (2) -> 64 cols

    const int h0 = blockIdx.y * MH;
    const int w0 = blockIdx.x * MW;
    const int co0 = blockIdx.z * 128;

    // ---- zero row ----
    if (tid < 16) *(uint4*)(smem + ZOFF + tid * 16) = make_uint4(0, 0, 0, 0);

    // ---- stage A halo band 10x18 pixels x 128 ch (once), swizzled ----
#pragma unroll
    for (int it = 0; it < 23; ++it) {
        const int sidx = tid + it * 128;       // 0..2943
        if (sidx < 2880) {
            const int slot = sidx >> 4;
            const int ch = sidx & 15;
            const int sw = ch ^ (slot & 7);
            const int bi = slot / 18;
            const int bj = slot - bi * 18;
            const int hh = h0 + bi - 1, ww = w0 + bj - 1;
            const bool ok = ((unsigned)hh < IH) & ((unsigned)ww < IW);
            cp16(sb + (uint32_t)(slot * PITCH + sw * 16),
                 g_xh + (ok ? ((hh * IW + ww) * CI + ch * 8) : 0), ok ? 16 : 0);
        }
    }
    issue_B(sb, 0, 0, co0, tid);   // commits halo + B0 as one group

    float acc[4][8][4];
#pragma unroll
    for (int mt = 0; mt < 4; ++mt)
#pragma unroll
        for (int nt = 0; nt < 8; ++nt)
#pragma unroll
            for (int j = 0; j < 4; ++j) acc[mt][nt][j] = 0.f;

    // per-lane A row coords (i, j) within 8x16 tile, per mt block (4 x 16 rows)
    int iRow[4], jCol[4];
#pragma unroll
    for (int mt = 0; mt < 4; ++mt) {
        const int m = wm * 64 + mt * 16 + ((lane >> 3) & 1) * 8 + (lane & 7);
        iRow[mt] = m >> 4;
        jCol[mt] = m & 15;
    }
    const uint32_t ahb = (uint32_t)((lane >> 4) & 1);   // A k-half chunk bit

    // B merged-x4: per-lane row and row&7; chunk = kk*2 + (g&1), swizzled.
    uint32_t bRowOff[4], bR7[4], bhb;
    {
        const int g = lane >> 3;
        bhb = (uint32_t)(g & 1);
#pragma unroll
        for (int np = 0; np < 4; ++np) {
            const int nt = np * 2 + (g >> 1);
            const int row = wn * 64 + nt * 8 + (lane & 7);
            bRowOff[np] = (uint32_t)(row * PITCH);
            bR7[np] = (uint32_t)(row & 7);
        }
    }

    for (int tap = 0; tap < 9; ++tap) {
        CP_WAIT(0);
        __syncthreads();
        if (tap < 8) issue_B(sb, (tap + 1) & 1, tap + 1, co0, tid);

        const int kh = tap / 3, kw = tap - (tap / 3) * 3;
        uint32_t aRowBase[4], aS7[4];
#pragma unroll
        for (int mt = 0; mt < 4; ++mt) {
            const int bi = iRow[mt] + kh;      // 0..9
            const int bj = jCol[mt] + kw;      // 0..17
            const int hh = h0 + bi - 1, ww = w0 + bj - 1;
            const bool ok = ((unsigned)hh < IH) & ((unsigned)ww < IW);
            const int slot = bi * 18 + bj;
            aRowBase[mt] = sb + (ok ? (uint32_t)(slot * PITCH) : (uint32_t)ZOFF);
            aS7[mt] = ok ? (uint32_t)(slot & 7) : 0u;
        }
        const uint32_t B = sb + BOFF + (uint32_t)(tap & 1) * BARR;

#pragma unroll
        for (int kk = 0; kk < 8; ++kk) {
            const uint32_t c2 = (uint32_t)(kk << 1);
            uint32_t af[4][4], bf[4][4];
#pragma unroll
            for (int mt = 0; mt < 4; ++mt)
                ldmx4(af[mt], aRowBase[mt] + (((c2 | ahb) ^ aS7[mt]) << 4));
#pragma unroll
            for (int np = 0; np < 4; ++np)
                ldmx4(bf[np], B + bRowOff[np] + (((c2 | bhb) ^ bR7[np]) << 4));
#pragma unroll
            for (int mt = 0; mt < 4; ++mt)
#pragma unroll
                for (int nt = 0; nt < 8; ++nt)
                    mma_f16(acc[mt][nt], af[mt], &bf[nt >> 1][(nt & 1) * 2]);
        }
    }

    // ---- epilogue: ReLU + float2 stores ----
#pragma unroll
    for (int mt = 0; mt < 4; ++mt) {
        const int m0 = wm * 64 + mt * 16 + (lane >> 2);   // tile row index
        const int i = m0 >> 4;
        const int j = m0 & 15;                             // 0..7
#pragma unroll
        for (int nt = 0; nt < 8; ++nt) {
            const int col = co0 + wn * 64 + nt * 8 + (lane & 3) * 2;
            float2 v0, v1;
            v0.x = fmaxf(acc[mt][nt][0], 0.f);
            v0.y = fmaxf(acc[mt][nt][1], 0.f);
            v1.x = fmaxf(acc[mt][nt][2], 0.f);
            v1.y = fmaxf(acc[mt][nt][3], 0.f);
            // rows m0 and m0+8 share i, differ by +8 in j
            *(float2*)(out + ((size_t)(h0 + i) * IW + w0 + j) * CO + col) = v0;
            *(float2*)(out + ((size_t)(h0 + i) * IW + w0 + j + 8) * CO + col) = v1;
        }
    }
}

// ======================= launch =======================
extern "C" void kernel_launch(void* const* d_in, const int* in_sizes, int n_in,
                              void* d_out, int out_size) {
    const float* x = (const float*)d_in[0];   // 224*224*128
    const float* W = (const float*)d_in[1];   // 256*1152
    float* out = (float*)d_out;

    cudaFuncSetAttribute(conv_mma_kernel,
                         cudaFuncAttributeMaxDynamicSharedMemorySize, SMEM_TOTAL);

    cvt_kernel<<<((NX + NW) / 8 + 255) / 256, 256>>>(x, W);
    conv_mma_kernel<<<dim3(IW / MW, IH / MH, CO / 128), 128, SMEM_TOTAL>>>(out);
}